// round 13
// baseline (speedup 1.0000x reference)
#include <cuda_runtime.h>
#include <cstdint>

// ---------------------------------------------------------------------------
// Problem constants
// ---------------------------------------------------------------------------
#define BATCH 64
#define SEQ   512
#define DIM   768
#define BD    (BATCH * DIM)          // 49152
#define R192  192
#define KDIM  1536
#define PREDK 2304

#define KS_FC1  4                    // 1536 = 4 * 384
#define KS_PRED 4                    // 2304 = 4 * 576

#define FC1_MN  (R192 * 512)         // 98304
#define PRED_MN (BATCH * 512)        // 32768

// smem: 2 stages x (As[32][72] + Bs[32][72]) floats = 36864 B (static)
#define AS_PITCH 72
#define AS_F     (32 * AS_PITCH)     // 2304
#define STAGE_F  (2 * AS_F)          // 4608

// ---------------------------------------------------------------------------
// Device scratch
// ---------------------------------------------------------------------------
__device__ float g_ent  [BATCH * PREDK];
__device__ float g_e    [3 * BD];              // entity state [r][d], r=k*64+b
__device__ float g_X1   [R192 * KDIM];         // fc1 input  [eA | eB]
__device__ float g_X2   [R192 * KDIM];         // gate input [u  | e ]
__device__ float g_mp   [768 * DIM];           // maxpool segment partials
__device__ float g_pfc1 [KS_FC1  * FC1_MN];
__device__ float g_ppred[KS_PRED * PRED_MN];

// ---------------------------------------------------------------------------
// Helpers
// ---------------------------------------------------------------------------
__device__ __forceinline__ float sigmoidf(float x) {
    return 1.0f / (1.0f + expf(-x));
}
__device__ __forceinline__ float4 ldg4(const float* p) {
    return __ldg(reinterpret_cast<const float4*>(p));
}
__device__ __forceinline__ float2 ldg2(const float* p) {
    return __ldg(reinterpret_cast<const float2*>(p));
}
__device__ __forceinline__ float f2tf32f(float x) {
    uint32_t r;
    asm("cvt.rna.tf32.f32 %0, %1;" : "=r"(r) : "f"(x));
    return __uint_as_float(r);
}
__device__ __forceinline__ void mma_tf32(float* d,
    uint32_t a0, uint32_t a1, uint32_t a2, uint32_t a3,
    uint32_t b0, uint32_t b1)
{
    asm volatile(
        "mma.sync.aligned.m16n8k8.row.col.f32.tf32.tf32.f32 "
        "{%0,%1,%2,%3}, {%4,%5,%6,%7}, {%8,%9}, {%0,%1,%2,%3};"
        : "+f"(d[0]), "+f"(d[1]), "+f"(d[2]), "+f"(d[3])
        : "r"(a0), "r"(a1), "r"(a2), "r"(a3), "r"(b0), "r"(b1));
}

// X1 slot tables. Pairs: p0=[e1|e2], p1=[e0|e2], p2=[e0|e1]
__device__ __constant__ int D1ROW[3] = {1, 0, 0};
__device__ __constant__ int D1OFF[3] = {0, 0, 768};
__device__ __constant__ int D2ROW[3] = {2, 2, 1};
__device__ __constant__ int D2OFF[3] = {0, 768, 768};

// ---------------------------------------------------------------------------
// Stage store: A (k-major, tf32-converted, scalar scatter) + B (k-major, f4)
// ---------------------------------------------------------------------------
__device__ __forceinline__ void stage_store(float* stage, int am, int akq,
                                            int bkk, int bnq,
                                            float4 Ar0, float4 Ar1,
                                            float4 Br0, float4 Br1)
{
    float* As = stage;
    float* Bs = stage + AS_F;
    As[(akq + 0) * AS_PITCH + am] = f2tf32f(Ar0.x);
    As[(akq + 1) * AS_PITCH + am] = f2tf32f(Ar0.y);
    As[(akq + 2) * AS_PITCH + am] = f2tf32f(Ar0.z);
    As[(akq + 3) * AS_PITCH + am] = f2tf32f(Ar0.w);
    As[(akq + 4) * AS_PITCH + am] = f2tf32f(Ar1.x);
    As[(akq + 5) * AS_PITCH + am] = f2tf32f(Ar1.y);
    As[(akq + 6) * AS_PITCH + am] = f2tf32f(Ar1.z);
    As[(akq + 7) * AS_PITCH + am] = f2tf32f(Ar1.w);
    float4 v0 = make_float4(f2tf32f(Br0.x), f2tf32f(Br0.y),
                            f2tf32f(Br0.z), f2tf32f(Br0.w));
    float4 v1 = make_float4(f2tf32f(Br1.x), f2tf32f(Br1.y),
                            f2tf32f(Br1.z), f2tf32f(Br1.w));
    *(float4*)&Bs[bkk * AS_PITCH + bnq]     = v0;
    *(float4*)&Bs[bkk * AS_PITCH + bnq + 4] = v1;
}

// ---------------------------------------------------------------------------
// GEMM core (one 256-thread block): acc[4][4] = A[64xK] * W[Kx64-of-N]
// ---------------------------------------------------------------------------
__device__ __forceinline__ void gemm_core_blk(float* sbase,
                          const float* __restrict__ A, int lda,
                          const float* __restrict__ W, int N,
                          int kchunk, float acc[4][4])
{
    const int ht = threadIdx.x;
    const int lane = ht & 31;
    const int wrp  = ht >> 5;
    const int wm = wrp & 3;
    const int wn = wrp >> 2;
    const int g = lane >> 2;
    const int t = lane & 3;

    const int am  = ht & 63;
    const int akq = (ht >> 6) * 8;
    const int bkk = ht >> 3;
    const int bnq = (ht & 7) * 8;

    #pragma unroll
    for (int f = 0; f < 4; f++)
        #pragma unroll
        for (int i = 0; i < 4; i++) acc[f][i] = 0.0f;

    const int T = kchunk >> 5;
    const float* Abase = A + (size_t)am * lda + akq;
    const float* Wbase = W + (size_t)bkk * N + bnq;

    float4 Ar0 = *(const float4*)(Abase);
    float4 Ar1 = *(const float4*)(Abase + 4);
    float4 Br0 = ldg4(Wbase);
    float4 Br1 = ldg4(Wbase + 4);

    stage_store(sbase, am, akq, bkk, bnq, Ar0, Ar1, Br0, Br1);
    if (T > 1) {
        Ar0 = *(const float4*)(Abase + 32);
        Ar1 = *(const float4*)(Abase + 36);
        const float* wp = Wbase + 32 * N;
        Br0 = ldg4(wp);
        Br1 = ldg4(wp + 4);
    }
    __syncthreads();

    int p = 0;
    for (int tt = 0; tt < T; tt++) {
        const float* As = sbase + p * STAGE_F;
        const float* Bs = As + AS_F;
        const float* Ab = As + wm * 16;
        const float* Bb = Bs + wn * 32;
        #pragma unroll
        for (int q = 0; q < 4; q++) {
            const int kr = q * 8 + t;
            uint32_t a0 = __float_as_uint(Ab[kr * AS_PITCH + g]);
            uint32_t a1 = __float_as_uint(Ab[kr * AS_PITCH + g + 8]);
            uint32_t a2 = __float_as_uint(Ab[(kr + 4) * AS_PITCH + g]);
            uint32_t a3 = __float_as_uint(Ab[(kr + 4) * AS_PITCH + g + 8]);
            #pragma unroll
            for (int f = 0; f < 4; f++) {
                uint32_t b0 = __float_as_uint(Bb[kr * AS_PITCH + f * 8 + g]);
                uint32_t b1 = __float_as_uint(Bb[(kr + 4) * AS_PITCH + f * 8 + g]);
                mma_tf32(acc[f], a0, a1, a2, a3, b0, b1);
            }
        }

        if (tt + 1 < T) {
            stage_store(sbase + (1 - p) * STAGE_F, am, akq, bkk, bnq,
                        Ar0, Ar1, Br0, Br1);
            if (tt + 2 < T) {
                int kb = (tt + 2) << 5;
                Ar0 = *(const float4*)(Abase + kb);
                Ar1 = *(const float4*)(Abase + kb + 4);
                const float* wp = Wbase + (size_t)kb * N;
                Br0 = ldg4(wp);
                Br1 = ldg4(wp + 4);
            }
            __syncthreads();
            p ^= 1;
        }
    }
}

__device__ __forceinline__ void gemm_tile_blk(float* sbase,
                          const float* __restrict__ A, int lda,
                          const float* __restrict__ W, int N,
                          float* __restrict__ Pout, int kchunk)
{
    float acc[4][4];
    gemm_core_blk(sbase, A, lda, W, N, kchunk, acc);

    const int ht = threadIdx.x;
    const int lane = ht & 31;
    const int wrp  = ht >> 5;
    const int wm = wrp & 3, wn = wrp >> 2;
    const int g = lane >> 2, t = lane & 3;
    const int row0 = wm * 16 + g;
    float* r0p = Pout + (size_t)row0 * N;
    float* r1p = r0p + 8 * N;
    #pragma unroll
    for (int f = 0; f < 4; f++) {
        int col = wn * 32 + f * 8 + 2 * t;
        *(float2*)(r0p + col) = make_float2(acc[f][0], acc[f][1]);
        *(float2*)(r1p + col) = make_float2(acc[f][2], acc[f][3]);
    }
}

// ---------------------------------------------------------------------------
// Kernel: maxpool segments. block = bk*4 + seg; threads 0..191 own f4 cols.
// ---------------------------------------------------------------------------
__global__ void __launch_bounds__(256)
maxpool_seg_kernel(const float* __restrict__ enc, const int* __restrict__ ep)
{
    int ht = threadIdx.x;
    if (ht >= 192) return;
    int job = blockIdx.x;
    int bk = job >> 2, seg = job & 3;
    int b = bk / 3;
    int s0 = ep[bk * 2 + 0];
    int s1 = ep[bk * 2 + 1];
    int lo = max(s0, seg * 128);
    int hi = min(s1, seg * 128 + 127);

    float4 m = make_float4(-1e30f, -1e30f, -1e30f, -1e30f);
    const float* base = enc + (size_t)b * SEQ * DIM + ht * 4;
    #pragma unroll 4
    for (int s = lo; s <= hi; s++) {
        float4 v = ldg4(base + (size_t)s * DIM);
        m.x = fmaxf(m.x, v.x); m.y = fmaxf(m.y, v.y);
        m.z = fmaxf(m.z, v.z); m.w = fmaxf(m.w, v.w);
    }
    *(float4*)(g_mp + (size_t)job * DIM + ht * 4) = m;
}

// ---------------------------------------------------------------------------
// Kernel: maxpool combine + scatter + entity score. block = bk.
// ---------------------------------------------------------------------------
__global__ void __launch_bounds__(256)
maxpool_combine_kernel(const float* __restrict__ projW,
                       const float* __restrict__ projb,
                       float* __restrict__ out_score)
{
    __shared__ float red[8];
    int ht = threadIdx.x;
    int bk = blockIdx.x;
    int b = bk / 3, k = bk - b * 3;
    float dv = 0.0f;

    if (ht < 192) {
        const float* mp = g_mp + (size_t)bk * 4 * DIM + ht * 4;
        float4 m0 = *(const float4*)(mp);
        float4 m1 = *(const float4*)(mp + DIM);
        float4 m2 = *(const float4*)(mp + 2 * DIM);
        float4 m3 = *(const float4*)(mp + 3 * DIM);
        float4 m;
        m.x = fmaxf(fmaxf(m0.x, m1.x), fmaxf(m2.x, m3.x));
        m.y = fmaxf(fmaxf(m0.y, m1.y), fmaxf(m2.y, m3.y));
        m.z = fmaxf(fmaxf(m0.z, m1.z), fmaxf(m2.z, m3.z));
        m.w = fmaxf(fmaxf(m0.w, m1.w), fmaxf(m2.w, m3.w));

        int d0 = ht * 4;
        *(float4*)(g_ent + (size_t)b * PREDK + k * DIM + d0) = m;
        *(float4*)(g_e   + (size_t)(k * 64 + b) * DIM + d0) = m;
        *(float4*)(g_X1  + (size_t)(D1ROW[k] * 64 + b) * KDIM + D1OFF[k] + d0) = m;
        *(float4*)(g_X1  + (size_t)(D2ROW[k] * 64 + b) * KDIM + D2OFF[k] + d0) = m;
        *(float4*)(g_X2  + (size_t)(k * 64 + b) * KDIM + 768 + d0) = m;

        float4 pw = ldg4(projW + d0);
        dv = m.x * pw.x + m.y * pw.y + m.z * pw.z + m.w * pw.w;
    }
    #pragma unroll
    for (int off = 16; off > 0; off >>= 1)
        dv += __shfl_down_sync(0xffffffffu, dv, off);
    if ((ht & 31) == 0) red[ht >> 5] = dv;
    __syncthreads();
    if (ht == 0) {
        float s = red[0] + red[1] + red[2] + red[3] + red[4] + red[5];
        out_score[bk] = sigmoidf(s + projb[0]);
    }
}

// ---------------------------------------------------------------------------
// Kernel: fc1 GEMM partials (blocks 0..95) + pred GEMM (96..127, iter 0)
// ---------------------------------------------------------------------------
__global__ void __launch_bounds__(256)
fc1_gemm_kernel(const float* __restrict__ VrW1, const float* __restrict__ predW1)
{
    __shared__ __align__(16) float sbase[2 * STAGE_F];
    int job = blockIdx.x;
    if (job < 96) {
        int z = job / 24, rem = job % 24;          // z 0..3
        int m0 = (rem >> 3) * 64, n0 = (rem & 7) * 64;
        int k0 = z * 384;
        gemm_tile_blk(sbase,
                      g_X1 + (size_t)m0 * KDIM + k0, KDIM,
                      VrW1 + (size_t)k0 * 512 + n0, 512,
                      g_pfc1 + (size_t)z * FC1_MN + m0 * 512 + n0, 384);
    } else {
        int j = job - 96;                          // 0..31
        int z = j >> 3, n0 = (j & 7) * 64;         // z 0..3
        int k0 = z * 576;
        gemm_tile_blk(sbase,
                      g_ent + k0, PREDK,
                      predW1 + (size_t)k0 * 512 + n0, 512,
                      g_ppred + (size_t)z * PRED_MN + n0, 576);
    }
}

// ---------------------------------------------------------------------------
// Kernel: finish1 (blocks 0..191) + pred finish (192..255, iter 0)
// finish1 also refreshes X2 right half (e) for the gate GEMM.
// ---------------------------------------------------------------------------
__global__ void __launch_bounds__(256)
finish_kernel(const float* __restrict__ b1, const float* __restrict__ W2,
              const float* __restrict__ b2, const float* __restrict__ ArW,
              const float* __restrict__ Arb,
              const float* __restrict__ pb1, const float* __restrict__ pW2,
              const float* __restrict__ pb2, float* __restrict__ rel_out)
{
    __shared__ float sh_h[512];
    __shared__ float red[5 * 256];
    __shared__ float sh_s[8];
    int t = threadIdx.x;
    int blk = blockIdx.x;

    if (blk < 192) {
        int r = blk;
        for (int j = t; j < 512; j += 256) {
            float s = b1[j];
            #pragma unroll
            for (int z = 0; z < KS_FC1; z++)
                s += g_pfc1[(size_t)z * FC1_MN + r * 512 + j];
            sh_h[j] = fmaxf(s, 0.0f);
        }
        __syncthreads();

        float ps[5] = {0, 0, 0, 0, 0};
        for (int j = t; j < 512; j += 256) {
            float h = sh_h[j];
            #pragma unroll
            for (int c = 0; c < 5; c++) ps[c] += h * W2[j * 5 + c];
        }
        #pragma unroll
        for (int c = 0; c < 5; c++) red[c * 256 + t] = ps[c];
        __syncthreads();
        for (int off = 128; off > 0; off >>= 1) {
            if (t < off) {
                #pragma unroll
                for (int c = 0; c < 5; c++) red[c * 256 + t] += red[c * 256 + t + off];
            }
            __syncthreads();
        }
        if (t < 5) sh_s[t] = sigmoidf(red[t * 256] + b2[t]);
        __syncthreads();

        float s0 = sh_s[0], s1 = sh_s[1], s2 = sh_s[2], s3 = sh_s[3], s4 = sh_s[4];
        const float* epv = g_e + (size_t)r * DIM;
        float* up = g_X2 + (size_t)r * KDIM;          // u -> left half of X2
        for (int d = t; d < DIM; d += 256) {
            float a = Arb[d] + s0 * ArW[d] + s1 * ArW[DIM + d] + s2 * ArW[2 * DIM + d]
                    + s3 * ArW[3 * DIM + d] + s4 * ArW[4 * DIM + d];
            float e = epv[d];
            up[d] = a * e;
            up[768 + d] = e;                          // refresh X2 right (e)
        }
    } else {
        int b = blk - 192;
        for (int j = t; j < 512; j += 256) {
            float s = pb1[j];
            #pragma unroll
            for (int z = 0; z < KS_PRED; z++)
                s += g_ppred[(size_t)z * PRED_MN + b * 512 + j];
            sh_h[j] = fmaxf(s, 0.0f);
        }
        __syncthreads();

        float ps[5] = {0, 0, 0, 0, 0};
        for (int j = t; j < 512; j += 256) {
            float h = sh_h[j];
            #pragma unroll
            for (int c = 0; c < 5; c++) ps[c] += h * pW2[j * 5 + c];
        }
        #pragma unroll
        for (int c = 0; c < 5; c++) red[c * 256 + t] = ps[c];
        __syncthreads();
        for (int off = 128; off > 0; off >>= 1) {
            if (t < off) {
                #pragma unroll
                for (int c = 0; c < 5; c++) red[c * 256 + t] += red[c * 256 + t + off];
            }
            __syncthreads();
        }
        if (t < 5) rel_out[b * 5 + t] = red[t * 256] + pb2[t];
    }
}

// ---------------------------------------------------------------------------
// Kernel: fused gate GEMM (full K=1536) + sigmoid blend + scatter.
// 36 blocks = 3 m-tiles x 12 n-tiles. Each block's e-reads/writes cover
// exactly its own (row, col) range -> no cross-block races. X2 untouched.
// ---------------------------------------------------------------------------
__global__ void __launch_bounds__(256)
gate_fused_kernel(const float* __restrict__ gateW,
                  const float* __restrict__ gateb,
                  float* __restrict__ out_final, int last)
{
    __shared__ __align__(16) float sbase[2 * STAGE_F];
    int ti = blockIdx.x;
    int m0 = (ti / 12) * 64, n0 = (ti % 12) * 64;
    int p = m0 >> 6;

    float acc[4][4];
    gemm_core_blk(sbase,
                  g_X2 + (size_t)m0 * KDIM, KDIM,
                  gateW + n0, 768, KDIM, acc);

    const int ht = threadIdx.x;
    const int lane = ht & 31;
    const int wrp  = ht >> 5;
    const int wm = wrp & 3, wn = wrp >> 2;
    const int g = lane >> 2, t = lane & 3;

    #pragma unroll
    for (int f = 0; f < 4; f++) {
        const int cl = wn * 32 + f * 8 + 2 * t;
        const int nn = n0 + cl;
        float2 gb = ldg2(gateb + nn);
        #pragma unroll
        for (int rr = 0; rr < 2; rr++) {
            const int rl = wm * 16 + g + rr * 8;
            const int r  = m0 + rl;
            const int b  = r & 63;
            float sx = gb.x + acc[f][rr * 2 + 0];
            float sy = gb.y + acc[f][rr * 2 + 1];
            float2 uv = *(const float2*)(g_X2 + (size_t)r * KDIM + nn);
            float2 ev = *(const float2*)(g_e + (size_t)r * DIM + nn);
            float gx = sigmoidf(sx);
            float gy = sigmoidf(sy);
            float2 res = make_float2(gx * ev.x + (1.0f - gx) * uv.x,
                                     gy * ev.y + (1.0f - gy) * uv.y);
            if (last) {
                *(float2*)(out_final + (size_t)b * PREDK + p * DIM + nn) = res;
            } else {
                *(float2*)(g_e + (size_t)r * DIM + nn) = res;
                *(float2*)(g_X1 + (size_t)(D1ROW[p] * 64 + b) * KDIM + D1OFF[p] + nn) = res;
                *(float2*)(g_X1 + (size_t)(D2ROW[p] * 64 + b) * KDIM + D2OFF[p] + nn) = res;
            }
        }
    }
}

// ---------------------------------------------------------------------------
// Launcher: 17 kernel launches, graph-capturable, no allocations
// ---------------------------------------------------------------------------
extern "C" void kernel_launch(void* const* d_in, const int* in_sizes, int n_in,
                              void* d_out, int out_size)
{
    const float* encoding = (const float*)d_in[0];
    const int*   ent_pos  = (const int*)  d_in[1];
    const float* Ar_W     = (const float*)d_in[2];
    const float* Ar_b     = (const float*)d_in[3];
    const float* Vr_W1    = (const float*)d_in[4];
    const float* Vr_b1    = (const float*)d_in[5];
    const float* Vr_W2    = (const float*)d_in[6];
    const float* Vr_b2    = (const float*)d_in[7];
    const float* gate_W   = (const float*)d_in[8];
    const float* gate_b   = (const float*)d_in[9];
    const float* pred_W1  = (const float*)d_in[10];
    const float* pred_b1  = (const float*)d_in[11];
    const float* pred_W2  = (const float*)d_in[12];
    const float* pred_b2  = (const float*)d_in[13];
    const float* proj_W   = (const float*)d_in[14];
    const float* proj_b   = (const float*)d_in[15];

    float* out = (float*)d_out;
    float* out_rel   = out;              // (64,5)
    float* out_score = out + 320;        // (64,3)
    float* out_final = out + 512;        // (64,3,768)

    maxpool_seg_kernel<<<768, 256>>>(encoding, ent_pos);
    maxpool_combine_kernel<<<192, 256>>>(proj_W, proj_b, out_score);

    for (int it = 0; it < 5; it++) {
        int g1 = (it == 0) ? 128 : 96;
        fc1_gemm_kernel<<<g1, 256>>>(Vr_W1, pred_W1);
        int g2 = (it == 0) ? 256 : 192;
        finish_kernel<<<g2, 256>>>(Vr_b1, Vr_W2, Vr_b2, Ar_W, Ar_b,
                                   pred_b1, pred_W2, pred_b2, out_rel);
        gate_fused_kernel<<<36, 256>>>(gate_W, gate_b, out_final,
                                       (it == 4) ? 1 : 0);
    }

    (void)in_sizes; (void)n_in; (void)out_size;
}

// round 15
// speedup vs baseline: 1.9957x; 1.9957x over previous
#include <cuda_runtime.h>
#include <cstdint>

// ---------------------------------------------------------------------------
// Problem constants
// ---------------------------------------------------------------------------
#define BATCH 64
#define SEQ   512
#define DIM   768
#define BD    (BATCH * DIM)          // 49152
#define R192  192
#define KDIM  1536
#define PREDK 2304

#define KS_FC1  6                    // 1536 = 6 * 256
#define KS_GATE 4                    // 1536 = 4 * 384
#define KS_PRED 6                    // 2304 = 6 * 384

#define FC1_MN  (R192 * 512)         // 98304
#define GATE_MN (R192 * 768)         // 147456
#define PRED_MN (BATCH * 512)        // 32768

// smem: 2 stages x (As[32][72] + Bs[32][72]) floats = 36864 B (static)
#define AS_PITCH 72
#define AS_F     (32 * AS_PITCH)     // 2304
#define STAGE_F  (2 * AS_F)          // 4608

// ---------------------------------------------------------------------------
// Device scratch
// ---------------------------------------------------------------------------
__device__ float g_ent  [BATCH * PREDK];
__device__ float g_e    [3 * BD];              // entity state [r][d], r=k*64+b
__device__ float g_X1   [R192 * KDIM];         // fc1 input  [eA | eB]
__device__ float g_X2   [R192 * KDIM];         // gate input [u  | e ]
__device__ float g_mp   [768 * DIM];           // maxpool segment partials
__device__ float g_pfc1 [KS_FC1  * FC1_MN];
__device__ float g_pgate[KS_GATE * GATE_MN];
__device__ float g_ppred[KS_PRED * PRED_MN];

// ---------------------------------------------------------------------------
// Helpers
// ---------------------------------------------------------------------------
__device__ __forceinline__ float sigmoidf(float x) {
    return 1.0f / (1.0f + expf(-x));
}
__device__ __forceinline__ float4 ldg4(const float* p) {
    return __ldg(reinterpret_cast<const float4*>(p));
}
__device__ __forceinline__ float f2tf32f(float x) {
    uint32_t r;
    asm("cvt.rna.tf32.f32 %0, %1;" : "=r"(r) : "f"(x));
    return __uint_as_float(r);
}
__device__ __forceinline__ void mma_tf32(float* d,
    uint32_t a0, uint32_t a1, uint32_t a2, uint32_t a3,
    uint32_t b0, uint32_t b1)
{
    asm volatile(
        "mma.sync.aligned.m16n8k8.row.col.f32.tf32.tf32.f32 "
        "{%0,%1,%2,%3}, {%4,%5,%6,%7}, {%8,%9}, {%0,%1,%2,%3};"
        : "+f"(d[0]), "+f"(d[1]), "+f"(d[2]), "+f"(d[3])
        : "r"(a0), "r"(a1), "r"(a2), "r"(a3), "r"(b0), "r"(b1));
}

// X1 slot tables. Pairs: p0=[e1|e2], p1=[e0|e2], p2=[e0|e1]
__device__ __constant__ int D1ROW[3] = {1, 0, 0};
__device__ __constant__ int D1OFF[3] = {0, 0, 768};
__device__ __constant__ int D2ROW[3] = {2, 2, 1};
__device__ __constant__ int D2OFF[3] = {0, 768, 768};

// ---------------------------------------------------------------------------
// Stage store: A (k-major, tf32-converted, scalar scatter) + B (k-major, f4)
// ---------------------------------------------------------------------------
__device__ __forceinline__ void stage_store(float* stage, int am, int akq,
                                            int bkk, int bnq,
                                            float4 Ar0, float4 Ar1,
                                            float4 Br0, float4 Br1)
{
    float* As = stage;
    float* Bs = stage + AS_F;
    As[(akq + 0) * AS_PITCH + am] = f2tf32f(Ar0.x);
    As[(akq + 1) * AS_PITCH + am] = f2tf32f(Ar0.y);
    As[(akq + 2) * AS_PITCH + am] = f2tf32f(Ar0.z);
    As[(akq + 3) * AS_PITCH + am] = f2tf32f(Ar0.w);
    As[(akq + 4) * AS_PITCH + am] = f2tf32f(Ar1.x);
    As[(akq + 5) * AS_PITCH + am] = f2tf32f(Ar1.y);
    As[(akq + 6) * AS_PITCH + am] = f2tf32f(Ar1.z);
    As[(akq + 7) * AS_PITCH + am] = f2tf32f(Ar1.w);
    float4 v0 = make_float4(f2tf32f(Br0.x), f2tf32f(Br0.y),
                            f2tf32f(Br0.z), f2tf32f(Br0.w));
    float4 v1 = make_float4(f2tf32f(Br1.x), f2tf32f(Br1.y),
                            f2tf32f(Br1.z), f2tf32f(Br1.w));
    *(float4*)&Bs[bkk * AS_PITCH + bnq]     = v0;
    *(float4*)&Bs[bkk * AS_PITCH + bnq + 4] = v1;
}

// ---------------------------------------------------------------------------
// GEMM tile (one 256-thread block per job): C[64x64] = A[64xK] * W[Kx64-of-N]
// ---------------------------------------------------------------------------
__device__ __forceinline__ void gemm_tile_blk(float* sbase,
                          const float* __restrict__ A, int lda,
                          const float* __restrict__ W, int N,
                          float* __restrict__ Pout, int kchunk)
{
    const int ht = threadIdx.x;
    const int lane = ht & 31;
    const int wrp  = ht >> 5;
    const int wm = wrp & 3;
    const int wn = wrp >> 2;
    const int g = lane >> 2;
    const int t = lane & 3;

    const int am  = ht & 63;
    const int akq = (ht >> 6) * 8;
    const int bkk = ht >> 3;
    const int bnq = (ht & 7) * 8;

    float acc[4][4];
    #pragma unroll
    for (int f = 0; f < 4; f++)
        #pragma unroll
        for (int i = 0; i < 4; i++) acc[f][i] = 0.0f;

    const int T = kchunk >> 5;
    const float* Abase = A + (size_t)am * lda + akq;
    const float* Wbase = W + (size_t)bkk * N + bnq;

    float4 Ar0 = *(const float4*)(Abase);
    float4 Ar1 = *(const float4*)(Abase + 4);
    float4 Br0 = ldg4(Wbase);
    float4 Br1 = ldg4(Wbase + 4);

    stage_store(sbase, am, akq, bkk, bnq, Ar0, Ar1, Br0, Br1);
    if (T > 1) {
        Ar0 = *(const float4*)(Abase + 32);
        Ar1 = *(const float4*)(Abase + 36);
        const float* wp = Wbase + 32 * N;
        Br0 = ldg4(wp);
        Br1 = ldg4(wp + 4);
    }
    __syncthreads();

    int p = 0;
    for (int tt = 0; tt < T; tt++) {
        const float* As = sbase + p * STAGE_F;
        const float* Bs = As + AS_F;
        const float* Ab = As + wm * 16;
        const float* Bb = Bs + wn * 32;
        #pragma unroll
        for (int q = 0; q < 4; q++) {
            const int kr = q * 8 + t;
            uint32_t a0 = __float_as_uint(Ab[kr * AS_PITCH + g]);
            uint32_t a1 = __float_as_uint(Ab[kr * AS_PITCH + g + 8]);
            uint32_t a2 = __float_as_uint(Ab[(kr + 4) * AS_PITCH + g]);
            uint32_t a3 = __float_as_uint(Ab[(kr + 4) * AS_PITCH + g + 8]);
            #pragma unroll
            for (int f = 0; f < 4; f++) {
                uint32_t b0 = __float_as_uint(Bb[kr * AS_PITCH + f * 8 + g]);
                uint32_t b1 = __float_as_uint(Bb[(kr + 4) * AS_PITCH + f * 8 + g]);
                mma_tf32(acc[f], a0, a1, a2, a3, b0, b1);
            }
        }

        if (tt + 1 < T) {
            stage_store(sbase + (1 - p) * STAGE_F, am, akq, bkk, bnq,
                        Ar0, Ar1, Br0, Br1);
            if (tt + 2 < T) {
                int kb = (tt + 2) << 5;
                Ar0 = *(const float4*)(Abase + kb);
                Ar1 = *(const float4*)(Abase + kb + 4);
                const float* wp = Wbase + (size_t)kb * N;
                Br0 = ldg4(wp);
                Br1 = ldg4(wp + 4);
            }
            __syncthreads();
            p ^= 1;
        }
    }

    const int row0 = wm * 16 + g;
    float* r0p = Pout + (size_t)row0 * N;
    float* r1p = r0p + 8 * N;
    #pragma unroll
    for (int f = 0; f < 4; f++) {
        int col = wn * 32 + f * 8 + 2 * t;
        *(float2*)(r0p + col) = make_float2(acc[f][0], acc[f][1]);
        *(float2*)(r1p + col) = make_float2(acc[f][2], acc[f][3]);
    }
}

// ---------------------------------------------------------------------------
// Kernel: maxpool segments. block = bk*4 + seg; threads 0..191 own f4 cols.
// ---------------------------------------------------------------------------
__global__ void __launch_bounds__(256)
maxpool_seg_kernel(const float* __restrict__ enc, const int* __restrict__ ep)
{
    int ht = threadIdx.x;
    if (ht >= 192) return;
    int job = blockIdx.x;
    int bk = job >> 2, seg = job & 3;
    int b = bk / 3;
    int s0 = ep[bk * 2 + 0];
    int s1 = ep[bk * 2 + 1];
    int lo = max(s0, seg * 128);
    int hi = min(s1, seg * 128 + 127);

    float4 m = make_float4(-1e30f, -1e30f, -1e30f, -1e30f);
    const float* base = enc + (size_t)b * SEQ * DIM + ht * 4;
    #pragma unroll 4
    for (int s = lo; s <= hi; s++) {
        float4 v = ldg4(base + (size_t)s * DIM);
        m.x = fmaxf(m.x, v.x); m.y = fmaxf(m.y, v.y);
        m.z = fmaxf(m.z, v.z); m.w = fmaxf(m.w, v.w);
    }
    *(float4*)(g_mp + (size_t)job * DIM + ht * 4) = m;
}

// ---------------------------------------------------------------------------
// Kernel: maxpool combine + scatter + entity score. block = bk.
// ---------------------------------------------------------------------------
__global__ void __launch_bounds__(256)
maxpool_combine_kernel(const float* __restrict__ projW,
                       const float* __restrict__ projb,
                       float* __restrict__ out_score)
{
    __shared__ float red[8];
    int ht = threadIdx.x;
    int bk = blockIdx.x;
    int b = bk / 3, k = bk - b * 3;
    float dv = 0.0f;

    if (ht < 192) {
        const float* mp = g_mp + (size_t)bk * 4 * DIM + ht * 4;
        float4 m0 = *(const float4*)(mp);
        float4 m1 = *(const float4*)(mp + DIM);
        float4 m2 = *(const float4*)(mp + 2 * DIM);
        float4 m3 = *(const float4*)(mp + 3 * DIM);
        float4 m;
        m.x = fmaxf(fmaxf(m0.x, m1.x), fmaxf(m2.x, m3.x));
        m.y = fmaxf(fmaxf(m0.y, m1.y), fmaxf(m2.y, m3.y));
        m.z = fmaxf(fmaxf(m0.z, m1.z), fmaxf(m2.z, m3.z));
        m.w = fmaxf(fmaxf(m0.w, m1.w), fmaxf(m2.w, m3.w));

        int d0 = ht * 4;
        *(float4*)(g_ent + (size_t)b * PREDK + k * DIM + d0) = m;
        *(float4*)(g_e   + (size_t)(k * 64 + b) * DIM + d0) = m;
        *(float4*)(g_X1  + (size_t)(D1ROW[k] * 64 + b) * KDIM + D1OFF[k] + d0) = m;
        *(float4*)(g_X1  + (size_t)(D2ROW[k] * 64 + b) * KDIM + D2OFF[k] + d0) = m;
        *(float4*)(g_X2  + (size_t)(k * 64 + b) * KDIM + 768 + d0) = m;

        float4 pw = ldg4(projW + d0);
        dv = m.x * pw.x + m.y * pw.y + m.z * pw.z + m.w * pw.w;
    }
    #pragma unroll
    for (int off = 16; off > 0; off >>= 1)
        dv += __shfl_down_sync(0xffffffffu, dv, off);
    if ((ht & 31) == 0) red[ht >> 5] = dv;
    __syncthreads();
    if (ht == 0) {
        float s = red[0] + red[1] + red[2] + red[3] + red[4] + red[5];
        out_score[bk] = sigmoidf(s + projb[0]);
    }
}

// ---------------------------------------------------------------------------
// Kernel: fc1 GEMM partials (blocks 0..143) + pred GEMM (144..191, iter 0)
// ---------------------------------------------------------------------------
__global__ void __launch_bounds__(256)
fc1_gemm_kernel(const float* __restrict__ VrW1, const float* __restrict__ predW1)
{
    __shared__ __align__(16) float sbase[2 * STAGE_F];
    int job = blockIdx.x;
    if (job < 144) {
        int z = job / 24, rem = job % 24;          // z 0..5
        int m0 = (rem >> 3) * 64, n0 = (rem & 7) * 64;
        int k0 = z * 256;
        gemm_tile_blk(sbase,
                      g_X1 + (size_t)m0 * KDIM + k0, KDIM,
                      VrW1 + (size_t)k0 * 512 + n0, 512,
                      g_pfc1 + (size_t)z * FC1_MN + m0 * 512 + n0, 256);
    } else {
        int j = job - 144;                         // 0..47
        int z = j >> 3, n0 = (j & 7) * 64;         // z 0..5
        int k0 = z * 384;
        gemm_tile_blk(sbase,
                      g_ent + k0, PREDK,
                      predW1 + (size_t)k0 * 512 + n0, 512,
                      g_ppred + (size_t)z * PRED_MN + n0, 384);
    }
}

// ---------------------------------------------------------------------------
// Kernel: gate GEMM partials (144 blocks)
// ---------------------------------------------------------------------------
__global__ void __launch_bounds__(256)
gate_gemm_kernel(const float* __restrict__ gateW)
{
    __shared__ __align__(16) float sbase[2 * STAGE_F];
    int job = blockIdx.x;
    int z = job / 36, rem = job % 36;              // z 0..3
    int m0 = (rem / 12) * 64, n0 = (rem % 12) * 64;
    int k0 = z * 384;
    gemm_tile_blk(sbase,
                  g_X2 + (size_t)m0 * KDIM + k0, KDIM,
                  gateW + (size_t)k0 * 768 + n0, 768,
                  g_pgate + (size_t)z * GATE_MN + m0 * 768 + n0, 384);
}

// ---------------------------------------------------------------------------
// Kernel: finish1 (blocks 0..191) + pred finish (192..255, iter 0)
// ---------------------------------------------------------------------------
__global__ void __launch_bounds__(256)
finish_kernel(const float* __restrict__ b1, const float* __restrict__ W2,
              const float* __restrict__ b2, const float* __restrict__ ArW,
              const float* __restrict__ Arb,
              const float* __restrict__ pb1, const float* __restrict__ pW2,
              const float* __restrict__ pb2, float* __restrict__ rel_out)
{
    __shared__ float sh_h[512];
    __shared__ float red[5 * 256];
    __shared__ float sh_s[8];
    int t = threadIdx.x;
    int blk = blockIdx.x;

    if (blk < 192) {
        int r = blk;
        for (int j = t; j < 512; j += 256) {
            float s = b1[j];
            #pragma unroll
            for (int z = 0; z < KS_FC1; z++)
                s += g_pfc1[(size_t)z * FC1_MN + r * 512 + j];
            sh_h[j] = fmaxf(s, 0.0f);
        }
        __syncthreads();

        float ps[5] = {0, 0, 0, 0, 0};
        for (int j = t; j < 512; j += 256) {
            float h = sh_h[j];
            #pragma unroll
            for (int c = 0; c < 5; c++) ps[c] += h * W2[j * 5 + c];
        }
        #pragma unroll
        for (int c = 0; c < 5; c++) red[c * 256 + t] = ps[c];
        __syncthreads();
        for (int off = 128; off > 0; off >>= 1) {
            if (t < off) {
                #pragma unroll
                for (int c = 0; c < 5; c++) red[c * 256 + t] += red[c * 256 + t + off];
            }
            __syncthreads();
        }
        if (t < 5) sh_s[t] = sigmoidf(red[t * 256] + b2[t]);
        __syncthreads();

        float s0 = sh_s[0], s1 = sh_s[1], s2 = sh_s[2], s3 = sh_s[3], s4 = sh_s[4];
        const float* epv = g_e + (size_t)r * DIM;
        float* up = g_X2 + (size_t)r * KDIM;          // u -> left half of X2
        for (int d = t; d < DIM; d += 256) {
            float a = Arb[d] + s0 * ArW[d] + s1 * ArW[DIM + d] + s2 * ArW[2 * DIM + d]
                    + s3 * ArW[3 * DIM + d] + s4 * ArW[4 * DIM + d];
            up[d] = a * epv[d];
        }
    } else {
        int b = blk - 192;
        for (int j = t; j < 512; j += 256) {
            float s = pb1[j];
            #pragma unroll
            for (int z = 0; z < KS_PRED; z++)
                s += g_ppred[(size_t)z * PRED_MN + b * 512 + j];
            sh_h[j] = fmaxf(s, 0.0f);
        }
        __syncthreads();

        float ps[5] = {0, 0, 0, 0, 0};
        for (int j = t; j < 512; j += 256) {
            float h = sh_h[j];
            #pragma unroll
            for (int c = 0; c < 5; c++) ps[c] += h * pW2[j * 5 + c];
        }
        #pragma unroll
        for (int c = 0; c < 5; c++) red[c * 256 + t] = ps[c];
        __syncthreads();
        for (int off = 128; off > 0; off >>= 1) {
            if (t < off) {
                #pragma unroll
                for (int c = 0; c < 5; c++) red[c * 256 + t] += red[c * 256 + t + off];
            }
            __syncthreads();
        }
        if (t < 5) rel_out[b * 5 + t] = red[t * 256] + pb2[t];
    }
}

// ---------------------------------------------------------------------------
// Kernel: gate blend (144 blocks x 256 threads; one float4 each)
// ---------------------------------------------------------------------------
__global__ void __launch_bounds__(256)
blend_kernel(const float* __restrict__ gateb, float* __restrict__ out_final,
             int last)
{
    int q = blockIdx.x * 256 + threadIdx.x;      // < 36864
    int idx = q * 4;
    int r = idx / 768, n = idx - r * 768;
    int p = r >> 6, b = r & 63;
    float4 s = *(const float4*)(gateb + n);
    #pragma unroll
    for (int z = 0; z < KS_GATE; z++) {
        float4 pv = *(const float4*)(g_pgate + (size_t)z * GATE_MN + idx);
        s.x += pv.x; s.y += pv.y; s.z += pv.z; s.w += pv.w;
    }
    float4 uv = *(const float4*)(g_X2 + (size_t)r * KDIM + n);   // u
    float4 ev = *(const float4*)(g_e + idx);
    float4 res; float gg;
    gg = sigmoidf(s.x); res.x = gg * ev.x + (1.0f - gg) * uv.x;
    gg = sigmoidf(s.y); res.y = gg * ev.y + (1.0f - gg) * uv.y;
    gg = sigmoidf(s.z); res.z = gg * ev.z + (1.0f - gg) * uv.z;
    gg = sigmoidf(s.w); res.w = gg * ev.w + (1.0f - gg) * uv.w;
    if (last) {
        *(float4*)(out_final + (size_t)b * PREDK + p * DIM + n) = res;
    } else {
        *(float4*)(g_e + idx) = res;
        *(float4*)(g_X2 + (size_t)r * KDIM + 768 + n) = res;
        *(float4*)(g_X1 + (size_t)(D1ROW[p] * 64 + b) * KDIM + D1OFF[p] + n) = res;
        *(float4*)(g_X1 + (size_t)(D2ROW[p] * 64 + b) * KDIM + D2OFF[p] + n) = res;
    }
}

// ---------------------------------------------------------------------------
// Launcher: 22 kernel launches, graph-capturable, no allocations
// ---------------------------------------------------------------------------
extern "C" void kernel_launch(void* const* d_in, const int* in_sizes, int n_in,
                              void* d_out, int out_size)
{
    const float* encoding = (const float*)d_in[0];
    const int*   ent_pos  = (const int*)  d_in[1];
    const float* Ar_W     = (const float*)d_in[2];
    const float* Ar_b     = (const float*)d_in[3];
    const float* Vr_W1    = (const float*)d_in[4];
    const float* Vr_b1    = (const float*)d_in[5];
    const float* Vr_W2    = (const float*)d_in[6];
    const float* Vr_b2    = (const float*)d_in[7];
    const float* gate_W   = (const float*)d_in[8];
    const float* gate_b   = (const float*)d_in[9];
    const float* pred_W1  = (const float*)d_in[10];
    const float* pred_b1  = (const float*)d_in[11];
    const float* pred_W2  = (const float*)d_in[12];
    const float* pred_b2  = (const float*)d_in[13];
    const float* proj_W   = (const float*)d_in[14];
    const float* proj_b   = (const float*)d_in[15];

    float* out = (float*)d_out;
    float* out_rel   = out;              // (64,5)
    float* out_score = out + 320;        // (64,3)
    float* out_final = out + 512;        // (64,3,768)

    maxpool_seg_kernel<<<768, 256>>>(encoding, ent_pos);
    maxpool_combine_kernel<<<192, 256>>>(proj_W, proj_b, out_score);

    for (int it = 0; it < 5; it++) {
        int g1 = (it == 0) ? 192 : 144;
        fc1_gemm_kernel<<<g1, 256>>>(Vr_W1, pred_W1);
        int g2 = (it == 0) ? 256 : 192;
        finish_kernel<<<g2, 256>>>(Vr_b1, Vr_W2, Vr_b2, Ar_W, Ar_b,
                                   pred_b1, pred_W2, pred_b2, out_rel);
        gate_gemm_kernel<<<144, 256>>>(gate_W);
        blend_kernel<<<144, 256>>>(gate_b, out_final, (it == 4) ? 1 : 0);
    }

    (void)in_sizes; (void)n_in; (void)out_size;
}